// round 9
// baseline (speedup 1.0000x reference)
#include <cuda_runtime.h>
#include <cstdint>

#define FULL 0xFFFFFFFFu
#define LQ 32
#define MQ 32
#define CQ 96
#define SPB 8
#define MAXB 8192

__device__ float2 g_pn[MAXB];     // (per_sample_ce, nonempty)
__device__ unsigned g_done;       // zero-initialized; reset by last block

__device__ __forceinline__ unsigned forder(float f) {
    unsigned u = __float_as_uint(f);
    return (u & 0x80000000u) ? ~u : (u | 0x80000000u);
}

__global__ void __launch_bounds__(32 * SPB, 5) editloss_main(
    const float* __restrict__ x, const int* __restrict__ y,
    float* __restrict__ out, int B, int nblocks)
{
    __shared__ float ss[32 * SPB], sc[32 * SPB];
    __shared__ unsigned s_last;

    const int warp = threadIdx.x >> 5;
    const int lane = threadIdx.x & 31;
    const int b = blockIdx.x * SPB + warp;
    const bool act = (b < B);

    if (act) {
        const float4* xb4 = (const float4*)(x + (size_t)b * (LQ * CQ));
        const int t_reg = y[b * MQ + lane];

        // ---- softmax/argmax: one row per iteration, lane r keeps row r ----
        float my_lse = 0.f; int my_pred = 0;
        #pragma unroll 4
        for (int r = 0; r < LQ; ++r) {
            float4 v = (lane < 24) ? xb4[r * 24 + lane]
                                   : make_float4(-1e30f, -1e30f, -1e30f, -1e30f);
            float m = v.x; int idx = 4 * lane;
            if (v.y > m) { m = v.y; idx = 4 * lane + 1; }
            if (v.z > m) { m = v.z; idx = 4 * lane + 2; }
            if (v.w > m) { m = v.w; idx = 4 * lane + 3; }
            // 64-bit key: (orderable max) desc, then smallest index wins ties
            unsigned long long key =
                ((unsigned long long)forder(m) << 32) | (unsigned)(255 - idx);
            #pragma unroll
            for (int o = 16; o; o >>= 1) {
                unsigned long long ok = __shfl_xor_sync(FULL, key, o);
                if (ok > key) key = ok;
            }
            int widx = 255 - (int)(key & 0xFFu);
            unsigned ou = (unsigned)(key >> 32);
            float wm = __uint_as_float((ou & 0x80000000u) ? (ou ^ 0x80000000u) : ~ou);
            float s = __expf(v.x - wm) + __expf(v.y - wm)
                    + __expf(v.z - wm) + __expf(v.w - wm);
            #pragma unroll
            for (int o = 16; o; o >>= 1) s += __shfl_xor_sync(FULL, s, o);
            if (lane == r) { my_lse = wm + __logf(s); my_pred = widx; }
        }

        // ---- match mask: bit j = (pred_row == tgt_j), 32 pipelined shfls ----
        unsigned mmask = 0;
        #pragma unroll
        for (int o = 0; o < MQ; ++o) {
            int tc = __shfl_sync(FULL, t_reg, o);
            if (my_pred == tc) mmask |= 1u << o;
        }

        // ---- Levenshtein DP wavefront; move codes packed 2b/cell in regs ----
        const int i = lane + 1;           // lane owns row i
        int prev = 0, prev2 = 0;
        unsigned clo = 0, chi = 0;        // codes for j=1..16 / 17..32
        #pragma unroll 1
        for (int k = 2; k <= LQ + MQ; ++k) {
            int j = k - i;
            int upv = __shfl_up_sync(FULL, prev, 1);   // D[i-1, j]
            int dgv = __shfl_up_sync(FULL, prev2, 1);  // D[i-1, j-1]
            int lfv = prev;                            // D[i, j-1]
            if (lane == 0) { upv = j; dgv = j - 1; }
            if (j == 1)    { lfv = i; dgv = i - 1; }
            int cst = (int)(((mmask >> ((j - 1) & 31)) & 1u) ^ 1u);
            int v = min(min(upv, lfv) + 1, dgv + cst);
            if (j >= 1 && j <= MQ) {
                unsigned code = (dgv + cst == v) ? 0u : ((upv + 1 == v) ? 1u : 2u);
                unsigned sh = 2u * ((unsigned)(j - 1) & 15u);
                if (j <= 16) clo |= code << sh; else chi |= code << sh;
                prev2 = prev; prev = v;
            }
        }

        // ---- backtrace (uniform across lanes; lane n grabs n-th diag pair) ----
        int ii = LQ, jj = MQ, n = 0, my_xi = 0, my_yj = 0;
        #pragma unroll 1
        for (int st = 0; st < LQ + MQ; ++st) {
            unsigned w = __shfl_sync(FULL, (jj <= 16) ? clo : chi, (ii - 1) & 31);
            int code;
            if (ii > 0) code = (jj > 0) ? (int)((w >> (2u * ((unsigned)(jj - 1) & 15u))) & 3u) : 1;
            else        code = (jj > 0) ? 2 : 3;
            if (code == 0) {
                if (n == lane) { my_xi = ii - 1; my_yj = jj - 1; }
                ++n; --ii; --jj;
            } else if (code == 1) { --ii; }
            else if (code == 2)   { --jj; }
            if ((ii | jj) == 0) break;    // uniform early exit
        }

        // ---- CE over diagonal steps ----
        int   lab  = __shfl_sync(FULL, t_reg, my_yj & 31);
        float lsev = __shfl_sync(FULL, my_lse, my_xi & 31);
        const float* xb = x + (size_t)b * (LQ * CQ);
        float ce = 0.f;
        if (lane < n) ce = lsev - __ldg(xb + my_xi * CQ + lab);  // L2 hit
        #pragma unroll
        for (int o = 16; o; o >>= 1) ce += __shfl_xor_sync(FULL, ce, o);
        if (lane == 0)
            g_pn[b] = make_float2((n > 0) ? ce / (float)n : 0.f,
                                  (n > 0) ? 1.f : 0.f);
    }

    // ---- fused final reduction: last block to finish does it ----
    __syncthreads();
    if (threadIdx.x == 0) {
        __threadfence();
        unsigned t = atomicAdd(&g_done, 1u);
        s_last = (t == (unsigned)(nblocks - 1)) ? 1u : 0u;
    }
    __syncthreads();
    if (s_last) {
        __threadfence();
        const float4* p = (const float4*)g_pn;   // (per,non,per,non)
        float s = 0.f, c = 0.f;
        int n4 = B >> 1;
        for (int idx = threadIdx.x; idx < n4; idx += 32 * SPB) {
            float4 v = p[idx];
            s += v.x + v.z;
            c += v.y + v.w;
        }
        if ((B & 1) && threadIdx.x == 0) { float2 t2 = g_pn[B - 1]; s += t2.x; c += t2.y; }
        ss[threadIdx.x] = s; sc[threadIdx.x] = c;
        __syncthreads();
        #pragma unroll
        for (int o = 16 * SPB; o > 0; o >>= 1) {
            if ((int)threadIdx.x < o) {
                ss[threadIdx.x] += ss[threadIdx.x + o];
                sc[threadIdx.x] += sc[threadIdx.x + o];
            }
            __syncthreads();
        }
        if (threadIdx.x == 0) {
            out[0] = ss[0] / sc[0];
            g_done = 0;                    // reset for next graph replay
        }
    }
}

extern "C" void kernel_launch(void* const* d_in, const int* in_sizes, int n_in,
                              void* d_out, int out_size)
{
    const float* x = (const float*)d_in[0];
    const int*   y = (const int*)d_in[1];
    int B = in_sizes[2];
    if (B > MAXB) B = MAXB;

    int blocks = (B + SPB - 1) / SPB;
    editloss_main<<<blocks, 32 * SPB>>>(x, y, (float*)d_out, B, blocks);
}

// round 10
// speedup vs baseline: 1.7967x; 1.7967x over previous
#include <cuda_runtime.h>
#include <cstdint>

#define FULL 0xFFFFFFFFu
#define LQ 32
#define MQ 32
#define CQ 96
#define SPB 8
#define PADW 33
#define MAXB 8192

__device__ float2 g_pn[MAXB];     // (per_sample_ce, nonempty)
__device__ unsigned g_done;       // zero-init; reset by last block

__device__ __forceinline__ unsigned forder(float f) {
    unsigned u = __float_as_uint(f);
    return u ^ (unsigned)(((int)u >> 31) | 0x80000000);
}
__device__ __forceinline__ float ex2(float a) {
    float r; asm("ex2.approx.f32 %0, %1;" : "=f"(r) : "f"(a)); return r;
}

__global__ void __launch_bounds__(32 * SPB, 5) editloss_main(
    const float* __restrict__ x, const int* __restrict__ y,
    float* __restrict__ out, int B, int nblocks)
{
    __shared__ unsigned sEq[SPB * PADW];    // Eq word per column j
    __shared__ unsigned sDg[SPB * PADW];    // diag-move bitmask per column
    __shared__ unsigned sUp[SPB * PADW];    // up-move bitmask per column
    __shared__ unsigned sPair[SPB * PADW];  // (xi | yj<<6) per diag step
    __shared__ int      sN[SPB];
    __shared__ float    ss[32 * SPB], sc[32 * SPB];
    __shared__ unsigned s_last;

    const int warp = threadIdx.x >> 5;
    const int lane = threadIdx.x & 31;
    const int b = blockIdx.x * SPB + warp;
    const bool act = (b < B);

    float my_lse = 0.f; int my_pred = 0; int t_reg = 0;

    // ================= Phase 1: softmax/argmax + Eq masks (warp/sample) ====
    if (act) {
        const float4* xb4 = (const float4*)(x + (size_t)b * (LQ * CQ));
        t_reg = y[b * MQ + lane];

        #pragma unroll 4
        for (int r = 0; r < LQ; ++r) {
            float4 v = (lane < 24) ? xb4[r * 24 + lane]
                                   : make_float4(-1e30f, -1e30f, -1e30f, -1e30f);
            float m = v.x; int idx = 4 * lane;
            if (v.y > m) { m = v.y; idx = 4 * lane + 1; }
            if (v.z > m) { m = v.z; idx = 4 * lane + 2; }
            if (v.w > m) { m = v.w; idx = 4 * lane + 3; }
            unsigned fo = forder(m);
            unsigned wmax = __reduce_max_sync(FULL, fo);
            unsigned bal = __ballot_sync(FULL, fo == wmax);
            int widx = __shfl_sync(FULL, idx, __ffs((int)bal) - 1);
            // sum of exp(v)*2^14 = ex2(v*log2e + 14), fixed-point warp add
            float e0 = ex2(fmaf(v.x, 1.44269504f, 14.f));
            float e1 = ex2(fmaf(v.y, 1.44269504f, 14.f));
            float e2 = ex2(fmaf(v.z, 1.44269504f, 14.f));
            float e3 = ex2(fmaf(v.w, 1.44269504f, 14.f));
            int si = __float2int_rn((e0 + e1) + (e2 + e3));
            int stot = __reduce_add_sync(FULL, si);
            if (lane == r) {
                my_pred = widx;
                my_lse = __logf((float)stot) - 14.f * 0.69314718f;
            }
        }

        // match mask: lane=row r, bit j = (pred_r == tgt_j)
        unsigned mmask = 0;
        #pragma unroll
        for (int o = 0; o < MQ; ++o) {
            int tc = __shfl_sync(FULL, t_reg, o);
            if (my_pred == tc) mmask |= 1u << o;
        }
        // warp 32x32 bit transpose: lane j ends with Eq_j (bits over rows)
        unsigned w = mmask;
        {
            unsigned yv;
            yv = __shfl_xor_sync(FULL, w, 16);
            w = (lane & 16) ? ((w & 0xFFFF0000u) | ((yv >> 16) & 0x0000FFFFu))
                            : ((w & 0x0000FFFFu) | ((yv & 0x0000FFFFu) << 16));
            yv = __shfl_xor_sync(FULL, w, 8);
            w = (lane & 8) ? ((w & 0xFF00FF00u) | ((yv >> 8) & 0x00FF00FFu))
                           : ((w & 0x00FF00FFu) | ((yv & 0x00FF00FFu) << 8));
            yv = __shfl_xor_sync(FULL, w, 4);
            w = (lane & 4) ? ((w & 0xF0F0F0F0u) | ((yv >> 4) & 0x0F0F0F0Fu))
                           : ((w & 0x0F0F0F0Fu) | ((yv & 0x0F0F0F0Fu) << 4));
            yv = __shfl_xor_sync(FULL, w, 2);
            w = (lane & 2) ? ((w & 0xCCCCCCCCu) | ((yv >> 2) & 0x33333333u))
                           : ((w & 0x33333333u) | ((yv & 0x33333333u) << 2));
            yv = __shfl_xor_sync(FULL, w, 1);
            w = (lane & 1) ? ((w & 0xAAAAAAAAu) | ((yv >> 1) & 0x55555555u))
                           : ((w & 0x55555555u) | ((yv & 0x55555555u) << 1));
        }
        sEq[warp * PADW + lane] = w;
    }
    __syncthreads();

    // ============ Phase 2+3: Myers bit-parallel DP + backtrace =============
    // thread s (s<SPB) handles sample s of this block, bits = rows i=1..32
    if (threadIdx.x < SPB) {
        const int s = threadIdx.x;
        if (blockIdx.x * SPB + s < B) {
            unsigned pv = 0xFFFFFFFFu, mv = 0u;   // column 0: D[i][0]=i
            #pragma unroll 4
            for (int j = 0; j < MQ; ++j) {
                unsigned eq  = sEq[s * PADW + j];
                unsigned xv  = eq | mv;
                unsigned xh  = (((eq & pv) + pv) ^ pv) | eq;
                unsigned ph  = mv | ~(xh | pv);
                unsigned mh  = pv & xh;
                unsigned phs = (ph << 1) | 1u;    // dh(i-1,j), row0 boundary=+1
                unsigned mhs = mh << 1;
                unsigned pv2 = mhs | ~(xv | phs); // dv(i,j)==+1
                unsigned mv2 = phs & xv;          // dv(i,j)==-1
                // diag move: Eq, or D[i][j]-D[i-1][j-1] == 1
                unsigned dg = eq | (pv2 & ~phs & ~mhs) | (~pv2 & ~mv2 & phs);
                sDg[s * PADW + j] = dg;
                sUp[s * PADW + j] = pv2 & ~dg;
                pv = pv2; mv = mv2;
            }
            // backtrace, exact reference priority: diag > up > left
            int ii = LQ, jj = MQ, n = 0;
            unsigned dg = sDg[s * PADW + jj - 1];
            unsigned up = sUp[s * PADW + jj - 1];
            while ((ii | jj) != 0) {
                int code;
                if (ii > 0 && jj > 0) {
                    unsigned bit = 1u << (ii - 1);
                    code = (dg & bit) ? 0 : ((up & bit) ? 1 : 2);
                } else code = (ii > 0) ? 1 : 2;
                if (code == 0) {
                    sPair[s * PADW + n] =
                        (unsigned)(ii - 1) | ((unsigned)(jj - 1) << 6);
                    ++n; --ii; --jj;
                    if (jj > 0) { dg = sDg[s*PADW+jj-1]; up = sUp[s*PADW+jj-1]; }
                } else if (code == 1) { --ii; }
                else { --jj;
                    if (jj > 0) { dg = sDg[s*PADW+jj-1]; up = sUp[s*PADW+jj-1]; }
                }
            }
            sN[s] = n;
        }
    }
    __syncthreads();

    // ================= Phase 4: CE over diagonal steps (warp/sample) =======
    if (act) {
        int n = sN[warp];
        unsigned pr = sPair[warp * PADW + ((lane < n) ? lane : 0)];
        int xi = pr & 31;
        int yj = (pr >> 6) & 31;
        int lab = __shfl_sync(FULL, t_reg, yj);
        float lsev = __shfl_sync(FULL, my_lse, xi);
        float ce = 0.f;
        if (lane < n)
            ce = lsev - __ldg(x + (size_t)b * (LQ * CQ) + xi * CQ + lab);
        #pragma unroll
        for (int o = 16; o; o >>= 1) ce += __shfl_xor_sync(FULL, ce, o);
        if (lane == 0)
            g_pn[b] = make_float2((n > 0) ? ce / (float)n : 0.f,
                                  (n > 0) ? 1.f : 0.f);
    }

    // ================= fused final reduction (last block) ==================
    __syncthreads();
    if (threadIdx.x == 0) {
        __threadfence();
        unsigned t = atomicAdd(&g_done, 1u);
        s_last = (t == (unsigned)(nblocks - 1)) ? 1u : 0u;
    }
    __syncthreads();
    if (s_last) {
        __threadfence();
        const float4* p = (const float4*)g_pn;
        float s = 0.f, c = 0.f;
        int n4 = B >> 1;
        for (int idx = threadIdx.x; idx < n4; idx += 32 * SPB) {
            float4 v = p[idx];
            s += v.x + v.z;
            c += v.y + v.w;
        }
        if ((B & 1) && threadIdx.x == 0) { float2 t2 = g_pn[B-1]; s += t2.x; c += t2.y; }
        ss[threadIdx.x] = s; sc[threadIdx.x] = c;
        __syncthreads();
        #pragma unroll
        for (int o = 16 * SPB; o > 0; o >>= 1) {
            if ((int)threadIdx.x < o) {
                ss[threadIdx.x] += ss[threadIdx.x + o];
                sc[threadIdx.x] += sc[threadIdx.x + o];
            }
            __syncthreads();
        }
        if (threadIdx.x == 0) {
            out[0] = ss[0] / sc[0];
            g_done = 0;
        }
    }
}

extern "C" void kernel_launch(void* const* d_in, const int* in_sizes, int n_in,
                              void* d_out, int out_size)
{
    const float* x = (const float*)d_in[0];
    const int*   y = (const int*)d_in[1];
    int B = in_sizes[2];
    if (B > MAXB) B = MAXB;

    int blocks = (B + SPB - 1) / SPB;
    editloss_main<<<blocks, 32 * SPB>>>(x, y, (float*)d_out, B, blocks);
}